// round 1
// baseline (speedup 1.0000x reference)
#include <cuda_runtime.h>
#include <mma.h>

using namespace nvcuda;

// Problem constants (fixed shapes per reference)
#define BB   16          // batch
#define EE   8           // experts
#define CC   1024        // capacity per expert
#define DD   512         // d_model
#define FF   2048        // d_ff

// Tiling
#define BM   128
#define BN   128
#define BK   16
#define ASTR 20          // padded SMEM stride for A tile (BK + 4)
#define BSTR 132         // padded SMEM stride for B tile (BN + 4)

// 1 GiB scratch for H = gelu(X@W1+b1): B*E*C*F floats
__device__ float g_h[(size_t)BB * EE * CC * FF];

__device__ __forceinline__ float gelu_tanh(float x) {
    // JAX default gelu (approximate=True)
    float x3 = x * x * x;
    float t  = tanhf(0.7978845608028654f * (x + 0.044715f * x3));
    return 0.5f * x * (1.0f + t);
}

// Grouped GEMM: for group g (= b*E + e), C[g] = act(A[g] @ B[e] + bias[e])
// A: [M=1024, K] row-major (lda), B: [K, N] row-major (ldb), C: [M, N] (ldc)
// Aall==nullptr -> A comes from g_h; Call==nullptr -> C goes to g_h.
__global__ void __launch_bounds__(256, 1)
grouped_gemm_tf32x3(const float* __restrict__ Aall,
                    const float* __restrict__ Ball,
                    const float* __restrict__ biasAll,
                    float* __restrict__ Call,
                    int K, int lda, int ldb, int ldc,
                    long aStride, long bStride, long biasStride, long cStride,
                    int doGelu)
{
    extern __shared__ float sm[];
    float* As = sm;                    // [BM][ASTR]
    float* Bs = sm + BM * ASTR;        // [BK][BSTR]

    const int g = blockIdx.z;          // 0 .. B*E-1
    const int e = g % EE;

    const float* A    = (Aall ? Aall : (const float*)g_h) + (long)g * aStride;
    const float* Bw   = Ball + (long)e * bStride;
    const float* bias = biasAll + (long)e * biasStride;
    float*       C    = (Call ? Call : (float*)g_h) + (long)g * cStride;

    const int mBase = blockIdx.y * BM;
    const int nBase = blockIdx.x * BN;

    const int tid    = threadIdx.x;
    const int warpId = tid >> 5;
    const int warpM  = warpId & 1;     // 0..1  (rows of 64)
    const int warpN  = warpId >> 1;    // 0..3  (cols of 32)

    wmma::fragment<wmma::accumulator, 16, 16, 8, float> acc[4][2];
    #pragma unroll
    for (int mi = 0; mi < 4; mi++)
        #pragma unroll
        for (int ni = 0; ni < 2; ni++)
            wmma::fill_fragment(acc[mi][ni], 0.0f);

    for (int k0 = 0; k0 < K; k0 += BK) {
        // ---- load A tile: BM x BK (512 float4, 2 per thread) ----
        #pragma unroll
        for (int i = 0; i < 2; i++) {
            int linear = tid + i * 256;          // 0..511
            int row    = linear >> 2;            // 4 float4 per row of 16
            int c4     = linear & 3;
            float4 v = *(const float4*)&A[(long)(mBase + row) * lda + k0 + c4 * 4];
            *(float4*)&As[row * ASTR + c4 * 4] = v;
        }
        // ---- load B tile: BK x BN (512 float4, 2 per thread) ----
        #pragma unroll
        for (int i = 0; i < 2; i++) {
            int linear = tid + i * 256;
            int row    = linear >> 5;            // 32 float4 per row of 128
            int c4     = linear & 31;
            float4 v = *(const float4*)&Bw[(long)(k0 + row) * ldb + nBase + c4 * 4];
            *(float4*)&Bs[row * BSTR + c4 * 4] = v;
        }
        __syncthreads();

        #pragma unroll
        for (int kk = 0; kk < BK; kk += 8) {
            wmma::fragment<wmma::matrix_a, 16, 16, 8, wmma::precision::tf32, wmma::row_major> aH[4], aL[4];
            wmma::fragment<wmma::matrix_b, 16, 16, 8, wmma::precision::tf32, wmma::row_major> bH[2], bL[2];

            #pragma unroll
            for (int mi = 0; mi < 4; mi++) {
                wmma::load_matrix_sync(aH[mi], &As[(warpM * 64 + mi * 16) * ASTR + kk], ASTR);
                #pragma unroll
                for (int t = 0; t < aH[mi].num_elements; t++) {
                    float v  = aH[mi].x[t];
                    float hi = wmma::__float_to_tf32(v);
                    aH[mi].x[t] = hi;
                    aL[mi].x[t] = wmma::__float_to_tf32(v - hi);
                }
            }
            #pragma unroll
            for (int ni = 0; ni < 2; ni++) {
                wmma::load_matrix_sync(bH[ni], &Bs[kk * BSTR + warpN * 32 + ni * 16], BSTR);
                #pragma unroll
                for (int t = 0; t < bH[ni].num_elements; t++) {
                    float v  = bH[ni].x[t];
                    float hi = wmma::__float_to_tf32(v);
                    bH[ni].x[t] = hi;
                    bL[ni].x[t] = wmma::__float_to_tf32(v - hi);
                }
            }
            // 3xTF32: acc += aH*bH + aL*bH + aH*bL   (error ~2^-22)
            #pragma unroll
            for (int mi = 0; mi < 4; mi++)
                #pragma unroll
                for (int ni = 0; ni < 2; ni++) {
                    wmma::mma_sync(acc[mi][ni], aH[mi], bH[ni], acc[mi][ni]);
                    wmma::mma_sync(acc[mi][ni], aL[mi], bH[ni], acc[mi][ni]);
                    wmma::mma_sync(acc[mi][ni], aH[mi], bL[ni], acc[mi][ni]);
                }
        }
        __syncthreads();
    }

    // ---- epilogue: stage BMxBN in SMEM, apply bias (+gelu), vector store ----
    float* stage = sm;   // 128*128 floats = 64 KB (covered by dynamic smem)
    #pragma unroll
    for (int mi = 0; mi < 4; mi++)
        #pragma unroll
        for (int ni = 0; ni < 2; ni++)
            wmma::store_matrix_sync(&stage[(warpM * 64 + mi * 16) * BN + warpN * 32 + ni * 16],
                                    acc[mi][ni], BN, wmma::mem_row_major);
    __syncthreads();

    #pragma unroll
    for (int i = 0; i < 16; i++) {
        int linear = tid + i * 256;              // 0..4095 (float4 index)
        int row    = linear >> 5;                // 32 float4 per row
        int c4     = linear & 31;
        float4 v = *(float4*)&stage[row * BN + c4 * 4];
        int n = nBase + c4 * 4;
        v.x += bias[n + 0];
        v.y += bias[n + 1];
        v.z += bias[n + 2];
        v.w += bias[n + 3];
        if (doGelu) {
            v.x = gelu_tanh(v.x);
            v.y = gelu_tanh(v.y);
            v.z = gelu_tanh(v.z);
            v.w = gelu_tanh(v.w);
        }
        *(float4*)&C[(long)(mBase + row) * ldc + n] = v;
    }
}

extern "C" void kernel_launch(void* const* d_in, const int* in_sizes, int n_in,
                              void* d_out, int out_size)
{
    const float* inputs = (const float*)d_in[0];   // [B, E*C, D]
    const float* w1     = (const float*)d_in[1];   // [E, D, F]
    const float* b1     = (const float*)d_in[2];   // [E, F]
    const float* w2     = (const float*)d_in[3];   // [E, F, D]
    const float* b2     = (const float*)d_in[4];   // [E, D]
    float*       out    = (float*)d_out;           // [B, E*C, D]

    cudaFuncSetAttribute(grouped_gemm_tf32x3,
                         cudaFuncAttributeMaxDynamicSharedMemorySize, 65536);

    dim3 blk(256);
    const int groups = BB * EE;   // 128

    // GEMM1: H = gelu(X @ W1 + b1)   M=C=1024, K=D=512, N=F=2048, C -> g_h
    dim3 grid1(FF / BN, CC / BM, groups);
    grouped_gemm_tf32x3<<<grid1, blk, 65536>>>(
        inputs, w1, b1, nullptr,
        /*K*/DD, /*lda*/DD, /*ldb*/FF, /*ldc*/FF,
        /*aStride*/(long)CC * DD, /*bStride*/(long)DD * FF,
        /*biasStride*/FF, /*cStride*/(long)CC * FF,
        /*doGelu*/1);

    // GEMM2: Y = H @ W2 + b2         M=1024, K=F=2048, N=D=512, A <- g_h
    dim3 grid2(DD / BN, CC / BM, groups);
    grouped_gemm_tf32x3<<<grid2, blk, 65536>>>(
        nullptr, w2, b2, out,
        /*K*/FF, /*lda*/FF, /*ldb*/DD, /*ldc*/DD,
        /*aStride*/(long)CC * FF, /*bStride*/(long)FF * DD,
        /*biasStride*/DD, /*cStride*/(long)CC * DD,
        /*doGelu*/0);
}

// round 3
// speedup vs baseline: 3.0530x; 3.0530x over previous
#include <cuda_runtime.h>
#include <cuda_bf16.h>
#include <mma.h>
#include <cstdint>

using namespace nvcuda;

// ---------------- problem constants ----------------
#define BB 16
#define EE 8
#define CC 1024
#define DD 512
#define FF 2048

// ---------------- tiling ----------------
#define BM 128
#define BN 128
#define BK 32
#define KS 40                         // smem row stride (bf16 elems) = 80B: 16B-aligned, conflict-free
#define ARR_ELEMS (128 * KS)          // one operand array (rows x stride)
#define ARR_BYTES (ARR_ELEMS * 2)     // 10240
#define STAGE_BYTES (4 * ARR_BYTES)   // Ahi,Alo,Bhi,Blo = 40960
#define NSTAGE 3
#define SMEM_TOTAL (NSTAGE * STAGE_BYTES)   // 122880
#define EPI_LD 132                    // f32 staging stride for epilogue

// ---------------- scratch (device globals; no allocs) ----------------
__device__ __nv_bfloat16 g_Xhi[(size_t)BB * EE * CC * DD];
__device__ __nv_bfloat16 g_Xlo[(size_t)BB * EE * CC * DD];
__device__ __nv_bfloat16 g_W1hi[(size_t)EE * FF * DD];   // [e][n=F][k=D]
__device__ __nv_bfloat16 g_W1lo[(size_t)EE * FF * DD];
__device__ __nv_bfloat16 g_W2hi[(size_t)EE * DD * FF];   // [e][n=D][k=F]
__device__ __nv_bfloat16 g_W2lo[(size_t)EE * DD * FF];
__device__ __nv_bfloat16 g_Hhi[(size_t)BB * EE * CC * FF];
__device__ __nv_bfloat16 g_Hlo[(size_t)BB * EE * CC * FF];

// ---------------- PTX helpers ----------------
__device__ __forceinline__ uint32_t smem_u32(const void* p) {
    uint32_t a;
    asm("{ .reg .u64 t; cvta.to.shared.u64 t, %1; cvt.u32.u64 %0, t; }" : "=r"(a) : "l"(p));
    return a;
}
#define CP_ASYNC16(dst, src) \
    asm volatile("cp.async.cg.shared.global [%0], [%1], 16;" :: "r"(dst), "l"(src) : "memory")
#define CP_COMMIT()  asm volatile("cp.async.commit_group;" ::: "memory")
#define CP_WAIT2()   asm volatile("cp.async.wait_group 2;" ::: "memory")

// ---------------- math helpers ----------------
__device__ __forceinline__ float gelu_fast(float x) {
    // tanh-gelu via ex2.approx: tanh(u) = 1 - 2/(1 + e^{2u})
    float u = 0.7978845608028654f * fmaf(0.044715f * x, x * x, x);
    float y = 2.8853900817779268f * u;     // 2u / ln2
    float z;
    asm("ex2.approx.f32 %0, %1;" : "=f"(z) : "f"(y));
    float t = 1.0f - __fdividef(2.0f, z + 1.0f);
    return 0.5f * x * (1.0f + t);
}
__device__ __forceinline__ void split_bf16(float x, __nv_bfloat16& h, __nv_bfloat16& l) {
    h = __float2bfloat16_rn(x);
    l = __float2bfloat16_rn(x - __bfloat162float(h));
}
__device__ __forceinline__ unsigned pack2(__nv_bfloat16 a, __nv_bfloat16 b) {
    __nv_bfloat162 p = __halves2bfloat162(a, b);
    return *reinterpret_cast<unsigned*>(&p);
}

// ---------------- prepass: split-convert X (coalesced) ----------------
__global__ void split_convert(const float* __restrict__ src,
                              __nv_bfloat16* __restrict__ hi,
                              __nv_bfloat16* __restrict__ lo, size_t n4) {
    size_t i = blockIdx.x * (size_t)blockDim.x + threadIdx.x;
    if (i >= n4) return;
    float4 v = reinterpret_cast<const float4*>(src)[i];
    float xs[4] = {v.x, v.y, v.z, v.w};
    __nv_bfloat16 h[4], l[4];
#pragma unroll
    for (int j = 0; j < 4; j++) split_bf16(xs[j], h[j], l[j]);
    uint2 uh, ul;
    uh.x = pack2(h[0], h[1]); uh.y = pack2(h[2], h[3]);
    ul.x = pack2(l[0], l[1]); ul.y = pack2(l[2], l[3]);
    reinterpret_cast<uint2*>(hi)[i] = uh;
    reinterpret_cast<uint2*>(lo)[i] = ul;
}

// ---------------- prepass: tiled transpose+split  w[e][K][N] -> t[e][N][K] ----------------
// block = (32, 8); each block does a 32x32 tile of (k, n) for one expert.
__global__ void split_transpose(const float* __restrict__ w,
                                __nv_bfloat16* __restrict__ thi,
                                __nv_bfloat16* __restrict__ tlo,
                                int K, int N) {
    __shared__ float tile[32][33];
    const int e = blockIdx.z;
    const int k0 = blockIdx.y * 32;
    const int n0 = blockIdx.x * 32;
    const float* we = w + (size_t)e * K * N;

#pragma unroll
    for (int i = 0; i < 4; i++) {
        int k = k0 + threadIdx.y + i * 8;
        tile[threadIdx.y + i * 8][threadIdx.x] = we[(size_t)k * N + n0 + threadIdx.x];
    }
    __syncthreads();

    __nv_bfloat16* th = thi + (size_t)e * N * K;
    __nv_bfloat16* tl = tlo + (size_t)e * N * K;
#pragma unroll
    for (int i = 0; i < 4; i++) {
        int n = n0 + threadIdx.y + i * 8;
        float v = tile[threadIdx.x][threadIdx.y + i * 8];
        __nv_bfloat16 h, l;
        split_bf16(v, h, l);
        th[(size_t)n * K + k0 + threadIdx.x] = h;
        tl[(size_t)n * K + k0 + threadIdx.x] = l;
    }
}

// ---------------- main grouped GEMM (mma.sync bf16 x3, cp.async 3-stage) ----------------
// C[128x128] = A[128xK] @ Bmem[128xK]^T (+bias) ; mode0: gelu -> (Ohi,Olo) ; mode1: -> outF
__global__ void __launch_bounds__(256)
moe_gemm(const __nv_bfloat16* __restrict__ Ahi, const __nv_bfloat16* __restrict__ Alo,
         const __nv_bfloat16* __restrict__ Bhi, const __nv_bfloat16* __restrict__ Blo,
         const float* __restrict__ bias,
         float* __restrict__ outF,
         __nv_bfloat16* __restrict__ Ohi, __nv_bfloat16* __restrict__ Olo,
         int K, int Ntot, int mode)
{
    extern __shared__ char smc[];
    const uint32_t sbase = smem_u32(smc);
    const int tid = threadIdx.x;
    const int wid = tid >> 5;

    const int g = blockIdx.z;
    const int e = g & (EE - 1);
    const int mBase = blockIdx.y * BM;
    const int nBase = blockIdx.x * BN;

    const __nv_bfloat16* aH = Ahi + (size_t)g * CC * K + (size_t)mBase * K;
    const __nv_bfloat16* aL = Alo + (size_t)g * CC * K + (size_t)mBase * K;
    const __nv_bfloat16* bH = Bhi + (size_t)e * Ntot * K + (size_t)nBase * K;
    const __nv_bfloat16* bL = Blo + (size_t)e * Ntot * K + (size_t)nBase * K;

    const int KT = K / BK;

    // ---- stage loader: 128 rows x 64B per array, 4 arrays, 8 cp.async/thread ----
    auto loadStage = [&](int kt) {
        const int k0 = kt * BK;
        const uint32_t s = sbase + (uint32_t)((kt % NSTAGE) * STAGE_BYTES);
#pragma unroll
        for (int i = 0; i < 2; i++) {
            int idx = tid + i * 256;
            int row = idx >> 2, q = idx & 3;
            uint32_t d = s + (uint32_t)(row * (KS * 2) + q * 16);
            size_t go = (size_t)row * K + k0 + q * 8;
            CP_ASYNC16(d,                 aH + go);
            CP_ASYNC16(d + ARR_BYTES,     aL + go);
            CP_ASYNC16(d + 2 * ARR_BYTES, bH + go);
            CP_ASYNC16(d + 3 * ARR_BYTES, bL + go);
        }
    };

    wmma::fragment<wmma::accumulator, 16, 16, 16, float> acc[4][2];
#pragma unroll
    for (int mi = 0; mi < 4; mi++)
#pragma unroll
        for (int ni = 0; ni < 2; ni++)
            wmma::fill_fragment(acc[mi][ni], 0.0f);

    const int wm = (wid & 1) * 64;     // warp M offset (2 warps in M)
    const int wn = (wid >> 1) * 32;    // warp N offset (4 warps in N)

    loadStage(0); CP_COMMIT();
    loadStage(1); CP_COMMIT();

    for (int kt = 0; kt < KT; kt++) {
        __syncthreads();                         // WAR: everyone done with stage kt-1
        if (kt + 2 < KT) loadStage(kt + 2);
        CP_COMMIT();
        CP_WAIT2();                              // stage kt complete (this thread's groups)
        __syncthreads();                         // cross-thread visibility

        const __nv_bfloat16* sAh = (const __nv_bfloat16*)(smc + (kt % NSTAGE) * STAGE_BYTES);
        const __nv_bfloat16* sAl = sAh + ARR_ELEMS;
        const __nv_bfloat16* sBh = sAh + 2 * ARR_ELEMS;
        const __nv_bfloat16* sBl = sAh + 3 * ARR_ELEMS;

#pragma unroll
        for (int ks = 0; ks < 2; ks++) {
            wmma::fragment<wmma::matrix_a, 16, 16, 16, __nv_bfloat16, wmma::row_major> fah[4], fal[4];
            wmma::fragment<wmma::matrix_b, 16, 16, 16, __nv_bfloat16, wmma::col_major> fbh[2], fbl[2];
#pragma unroll
            for (int mi = 0; mi < 4; mi++)
                wmma::load_matrix_sync(fah[mi], sAh + (wm + mi * 16) * KS + ks * 16, KS);
#pragma unroll
            for (int ni = 0; ni < 2; ni++)
                wmma::load_matrix_sync(fbh[ni], sBh + (wn + ni * 16) * KS + ks * 16, KS);
#pragma unroll
            for (int mi = 0; mi < 4; mi++)
#pragma unroll
                for (int ni = 0; ni < 2; ni++)
                    wmma::mma_sync(acc[mi][ni], fah[mi], fbh[ni], acc[mi][ni]);

#pragma unroll
            for (int mi = 0; mi < 4; mi++)
                wmma::load_matrix_sync(fal[mi], sAl + (wm + mi * 16) * KS + ks * 16, KS);
#pragma unroll
            for (int mi = 0; mi < 4; mi++)
#pragma unroll
                for (int ni = 0; ni < 2; ni++)
                    wmma::mma_sync(acc[mi][ni], fal[mi], fbh[ni], acc[mi][ni]);

#pragma unroll
            for (int ni = 0; ni < 2; ni++)
                wmma::load_matrix_sync(fbl[ni], sBl + (wn + ni * 16) * KS + ks * 16, KS);
#pragma unroll
            for (int mi = 0; mi < 4; mi++)
#pragma unroll
                for (int ni = 0; ni < 2; ni++)
                    wmma::mma_sync(acc[mi][ni], fah[mi], fbl[ni], acc[mi][ni]);
        }
    }

    // ---- epilogue: stage f32 in smem, bias (+gelu), vector stores ----
    __syncthreads();                  // all warps done reading operand smem
    float* stage = reinterpret_cast<float*>(smc);
#pragma unroll
    for (int mi = 0; mi < 4; mi++)
#pragma unroll
        for (int ni = 0; ni < 2; ni++)
            wmma::store_matrix_sync(&stage[(wm + mi * 16) * EPI_LD + wn + ni * 16],
                                    acc[mi][ni], EPI_LD, wmma::mem_row_major);
    __syncthreads();

#pragma unroll
    for (int i = 0; i < 16; i++) {
        int idx = tid + i * 256;          // float4 index, 0..4095
        int row = idx >> 5;
        int c4 = idx & 31;
        float4 v = *reinterpret_cast<float4*>(&stage[row * EPI_LD + c4 * 4]);
        int n = nBase + c4 * 4;
        v.x += bias[n + 0]; v.y += bias[n + 1]; v.z += bias[n + 2]; v.w += bias[n + 3];
        size_t off = (size_t)g * CC * Ntot + (size_t)(mBase + row) * Ntot + n;
        if (mode == 0) {
            float g0 = gelu_fast(v.x), g1 = gelu_fast(v.y), g2 = gelu_fast(v.z), g3 = gelu_fast(v.w);
            __nv_bfloat16 h0, l0, h1, l1, h2, l2, h3, l3;
            split_bf16(g0, h0, l0); split_bf16(g1, h1, l1);
            split_bf16(g2, h2, l2); split_bf16(g3, h3, l3);
            uint2 uh = make_uint2(pack2(h0, h1), pack2(h2, h3));
            uint2 ul = make_uint2(pack2(l0, l1), pack2(l2, l3));
            *reinterpret_cast<uint2*>(Ohi + off) = uh;
            *reinterpret_cast<uint2*>(Olo + off) = ul;
        } else {
            *reinterpret_cast<float4*>(outF + off) = v;
        }
    }
}

// ---------------- host launcher ----------------
extern "C" void kernel_launch(void* const* d_in, const int* in_sizes, int n_in,
                              void* d_out, int out_size) {
    const float* inputs = (const float*)d_in[0];   // [B, E*C, D]
    const float* w1     = (const float*)d_in[1];   // [E, D, F]
    const float* b1     = (const float*)d_in[2];   // [E, F]
    const float* w2     = (const float*)d_in[3];   // [E, F, D]
    const float* b2     = (const float*)d_in[4];   // [E, D]
    float*       out    = (float*)d_out;           // [B, E*C, D]

    void *xhi, *xlo, *w1hi, *w1lo, *w2hi, *w2lo, *hhi, *hlo;
    cudaGetSymbolAddress(&xhi, g_Xhi);   cudaGetSymbolAddress(&xlo, g_Xlo);
    cudaGetSymbolAddress(&w1hi, g_W1hi); cudaGetSymbolAddress(&w1lo, g_W1lo);
    cudaGetSymbolAddress(&w2hi, g_W2hi); cudaGetSymbolAddress(&w2lo, g_W2lo);
    cudaGetSymbolAddress(&hhi, g_Hhi);   cudaGetSymbolAddress(&hlo, g_Hlo);

    cudaFuncSetAttribute(moe_gemm, cudaFuncAttributeMaxDynamicSharedMemorySize, SMEM_TOTAL);

    // prepass: split X, transpose+split weights
    {
        size_t n4 = (size_t)BB * EE * CC * DD / 4;
        split_convert<<<(unsigned)((n4 + 255) / 256), 256>>>(
            inputs, (__nv_bfloat16*)xhi, (__nv_bfloat16*)xlo, n4);
    }
    {
        dim3 blk(32, 8);
        dim3 g1(FF / 32, DD / 32, EE);
        split_transpose<<<g1, blk>>>(w1, (__nv_bfloat16*)w1hi, (__nv_bfloat16*)w1lo, DD, FF);
        dim3 g2(DD / 32, FF / 32, EE);
        split_transpose<<<g2, blk>>>(w2, (__nv_bfloat16*)w2hi, (__nv_bfloat16*)w2lo, FF, DD);
    }

    // GEMM1: H = gelu(X @ W1 + b1): per group M=1024, K=512, N=2048
    {
        dim3 grid(FF / BN, CC / BM, BB * EE);
        moe_gemm<<<grid, 256, SMEM_TOTAL>>>(
            (const __nv_bfloat16*)xhi, (const __nv_bfloat16*)xlo,
            (const __nv_bfloat16*)w1hi, (const __nv_bfloat16*)w1lo,
            b1, nullptr, (__nv_bfloat16*)hhi, (__nv_bfloat16*)hlo,
            DD, FF, 0);
    }
    // GEMM2: Y = H @ W2 + b2: per group M=1024, K=2048, N=512
    {
        dim3 grid(DD / BN, CC / BM, BB * EE);
        moe_gemm<<<grid, 256, SMEM_TOTAL>>>(
            (const __nv_bfloat16*)hhi, (const __nv_bfloat16*)hlo,
            (const __nv_bfloat16*)w2hi, (const __nv_bfloat16*)w2lo,
            b2, out, nullptr, nullptr,
            FF, DD, 1);
    }
}

// round 4
// speedup vs baseline: 10.6637x; 3.4929x over previous
#include <cuda_runtime.h>
#include <cuda_fp16.h>
#include <mma.h>
#include <cstdint>

using namespace nvcuda;

// ---------------- problem constants ----------------
#define BB 16
#define EE 8
#define CC 1024
#define DD 512
#define FF 2048

// ---------------- tiling ----------------
#define BM 128
#define BN 128
#define BK 64
#define KS 72                          // smem row stride in halfs (144B): 16B-aligned, LDSM conflict-free
#define A_ROWS 128
#define B_ROWS 128
#define STAGE_ELEMS ((A_ROWS + B_ROWS) * KS)
#define STAGE_BYTES (STAGE_ELEMS * 2)  // 36864
#define NSTAGE 3
#define SMEM_TOTAL (NSTAGE * STAGE_BYTES)   // 110592 -> 2 CTAs/SM
#define EPI_LD 132                     // f32 epilogue staging stride

// ---------------- scratch (device globals; no allocs) ----------------
__device__ __half g_Xh [(size_t)BB * EE * CC * DD];      // X  fp16
__device__ __half g_W1t[(size_t)EE * FF * DD];           // W1^T [e][n=F][k=D] fp16
__device__ __half g_W2t[(size_t)EE * DD * FF];           // W2^T [e][n=D][k=F] fp16
__device__ __half g_Hh [(size_t)BB * EE * CC * FF];      // H  fp16

// ---------------- PTX helpers ----------------
__device__ __forceinline__ uint32_t smem_u32(const void* p) {
    uint32_t a;
    asm("{ .reg .u64 t; cvta.to.shared.u64 t, %1; cvt.u32.u64 %0, t; }" : "=r"(a) : "l"(p));
    return a;
}
#define CP_ASYNC16(dst, src) \
    asm volatile("cp.async.cg.shared.global [%0], [%1], 16;" :: "r"(dst), "l"(src) : "memory")
#define CP_COMMIT()  asm volatile("cp.async.commit_group;" ::: "memory")
#define CP_WAIT1()   asm volatile("cp.async.wait_group 1;" ::: "memory")

// ---------------- math helpers ----------------
__device__ __forceinline__ float gelu_fast(float x) {
    // tanh-gelu via ex2.approx: tanh(u) = 1 - 2/(1 + e^{2u})
    float u = 0.7978845608028654f * fmaf(0.044715f * x, x * x, x);
    float y = 2.8853900817779268f * u;     // 2u / ln2
    float z;
    asm("ex2.approx.f32 %0, %1;" : "=f"(z) : "f"(y));
    float t = 1.0f - __fdividef(2.0f, z + 1.0f);
    return 0.5f * x * (1.0f + t);
}

// ---------------- prepass: fp32 -> fp16 (coalesced) ----------------
__global__ void to_fp16(const float* __restrict__ src, __half* __restrict__ dst, size_t n4) {
    size_t i = blockIdx.x * (size_t)blockDim.x + threadIdx.x;
    if (i >= n4) return;
    float4 v = reinterpret_cast<const float4*>(src)[i];
    __half2 h0 = __floats2half2_rn(v.x, v.y);
    __half2 h1 = __floats2half2_rn(v.z, v.w);
    uint2 u;
    u.x = *reinterpret_cast<unsigned*>(&h0);
    u.y = *reinterpret_cast<unsigned*>(&h1);
    reinterpret_cast<uint2*>(dst)[i] = u;
}

// ---------------- prepass: tiled transpose  w[e][K][N] -> t[e][N][K] fp16 ----------------
__global__ void transpose_fp16(const float* __restrict__ w, __half* __restrict__ t,
                               int K, int N) {
    __shared__ float tile[32][33];
    const int e = blockIdx.z;
    const int k0 = blockIdx.y * 32;
    const int n0 = blockIdx.x * 32;
    const float* we = w + (size_t)e * K * N;
#pragma unroll
    for (int i = 0; i < 4; i++) {
        int k = k0 + threadIdx.y + i * 8;
        tile[threadIdx.y + i * 8][threadIdx.x] = we[(size_t)k * N + n0 + threadIdx.x];
    }
    __syncthreads();
    __half* te = t + (size_t)e * N * K;
#pragma unroll
    for (int i = 0; i < 4; i++) {
        int n = n0 + threadIdx.y + i * 8;
        te[(size_t)n * K + k0 + threadIdx.x] = __float2half_rn(tile[threadIdx.x][threadIdx.y + i * 8]);
    }
}

// ---------------- main grouped GEMM (fp16 mma, cp.async 3-stage, 2 CTAs/SM) ----------------
// C[128x128] = A[128xK] @ B[128xK]^T + bias ; mode0: gelu -> Oh (fp16) ; mode1: -> outF (fp32)
__global__ void __launch_bounds__(256, 2)
moe_gemm(const __half* __restrict__ Ah, const __half* __restrict__ Bh,
         const float* __restrict__ bias,
         float* __restrict__ outF, __half* __restrict__ Oh,
         int K, int Ntot, int mode)
{
    extern __shared__ char smc[];
    const uint32_t sbase = smem_u32(smc);
    const int tid = threadIdx.x;
    const int wid = tid >> 5;

    const int g = blockIdx.z;
    const int e = g & (EE - 1);
    const int mBase = blockIdx.y * BM;
    const int nBase = blockIdx.x * BN;

    const __half* aP = Ah + (size_t)g * CC * K + (size_t)mBase * K;
    const __half* bP = Bh + (size_t)e * Ntot * K + (size_t)nBase * K;

    const int KT = K / BK;

    // stage loader: 256 rows x 128B  (8 cp.async16 per thread)
    auto loadStage = [&](int kt) {
        const int k0 = kt * BK;
        const uint32_t s = sbase + (uint32_t)((kt % NSTAGE) * STAGE_BYTES);
#pragma unroll
        for (int i = 0; i < 4; i++) {
            int idx = tid + i * 256;              // 0..1023
            int row = idx >> 3, q = idx & 7;      // 8 x 16B per row
            uint32_t d = s + (uint32_t)(row * (KS * 2) + q * 16);
            size_t go = (size_t)row * K + k0 + q * 8;
            CP_ASYNC16(d, aP + go);                                       // A rows 0..127
            CP_ASYNC16(d + A_ROWS * KS * 2, bP + go);                     // B rows 0..127
        }
    };

    wmma::fragment<wmma::accumulator, 16, 16, 16, float> acc[4][2];
#pragma unroll
    for (int mi = 0; mi < 4; mi++)
#pragma unroll
        for (int ni = 0; ni < 2; ni++)
            wmma::fill_fragment(acc[mi][ni], 0.0f);

    const int wm = (wid & 1) * 64;     // 2 warps in M
    const int wn = (wid >> 1) * 32;    // 4 warps in N

    loadStage(0); CP_COMMIT();
    loadStage(1); CP_COMMIT();

    for (int kt = 0; kt < KT; kt++) {
        CP_WAIT1();                    // stage kt complete
        __syncthreads();               // visibility + all threads done computing kt-1
        if (kt + 2 < KT) loadStage(kt + 2);
        CP_COMMIT();                   // unconditional: keeps group accounting uniform

        const __half* sA = (const __half*)(smc + (kt % NSTAGE) * STAGE_BYTES);
        const __half* sB = sA + A_ROWS * KS;

#pragma unroll
        for (int ks = 0; ks < 4; ks++) {
            wmma::fragment<wmma::matrix_a, 16, 16, 16, __half, wmma::row_major> fa[4];
            wmma::fragment<wmma::matrix_b, 16, 16, 16, __half, wmma::col_major> fb[2];
#pragma unroll
            for (int mi = 0; mi < 4; mi++)
                wmma::load_matrix_sync(fa[mi], sA + (wm + mi * 16) * KS + ks * 16, KS);
#pragma unroll
            for (int ni = 0; ni < 2; ni++)
                wmma::load_matrix_sync(fb[ni], sB + (wn + ni * 16) * KS + ks * 16, KS);
#pragma unroll
            for (int mi = 0; mi < 4; mi++)
#pragma unroll
                for (int ni = 0; ni < 2; ni++)
                    wmma::mma_sync(acc[mi][ni], fa[mi], fb[ni], acc[mi][ni]);
        }
    }

    // ---- epilogue: stage f32, bias (+gelu), vectorized stores ----
    __syncthreads();
    float* stage = reinterpret_cast<float*>(smc);
#pragma unroll
    for (int mi = 0; mi < 4; mi++)
#pragma unroll
        for (int ni = 0; ni < 2; ni++)
            wmma::store_matrix_sync(&stage[(wm + mi * 16) * EPI_LD + wn + ni * 16],
                                    acc[mi][ni], EPI_LD, wmma::mem_row_major);
    __syncthreads();

#pragma unroll
    for (int i = 0; i < 16; i++) {
        int idx = tid + i * 256;          // float4 index, 0..4095
        int row = idx >> 5;
        int c4 = idx & 31;
        float4 v = *reinterpret_cast<float4*>(&stage[row * EPI_LD + c4 * 4]);
        int n = nBase + c4 * 4;
        v.x += bias[n + 0]; v.y += bias[n + 1]; v.z += bias[n + 2]; v.w += bias[n + 3];
        size_t off = (size_t)g * CC * Ntot + (size_t)(mBase + row) * Ntot + n;
        if (mode == 0) {
            __half2 h0 = __floats2half2_rn(gelu_fast(v.x), gelu_fast(v.y));
            __half2 h1 = __floats2half2_rn(gelu_fast(v.z), gelu_fast(v.w));
            uint2 u;
            u.x = *reinterpret_cast<unsigned*>(&h0);
            u.y = *reinterpret_cast<unsigned*>(&h1);
            *reinterpret_cast<uint2*>(Oh + off) = u;
        } else {
            *reinterpret_cast<float4*>(outF + off) = v;
        }
    }
}

// ---------------- host launcher ----------------
extern "C" void kernel_launch(void* const* d_in, const int* in_sizes, int n_in,
                              void* d_out, int out_size) {
    const float* inputs = (const float*)d_in[0];   // [B, E*C, D]
    const float* w1     = (const float*)d_in[1];   // [E, D, F]
    const float* b1     = (const float*)d_in[2];   // [E, F]
    const float* w2     = (const float*)d_in[3];   // [E, F, D]
    const float* b2     = (const float*)d_in[4];   // [E, D]
    float*       out    = (float*)d_out;           // [B, E*C, D]

    void *xh, *w1t, *w2t, *hh;
    cudaGetSymbolAddress(&xh, g_Xh);
    cudaGetSymbolAddress(&w1t, g_W1t);
    cudaGetSymbolAddress(&w2t, g_W2t);
    cudaGetSymbolAddress(&hh, g_Hh);

    cudaFuncSetAttribute(moe_gemm, cudaFuncAttributeMaxDynamicSharedMemorySize, SMEM_TOTAL);

    // prepass
    {
        size_t n4 = (size_t)BB * EE * CC * DD / 4;
        to_fp16<<<(unsigned)((n4 + 255) / 256), 256>>>(inputs, (__half*)xh, n4);
    }
    {
        dim3 blk(32, 8);
        dim3 g1(FF / 32, DD / 32, EE);
        transpose_fp16<<<g1, blk>>>(w1, (__half*)w1t, DD, FF);
        dim3 g2(DD / 32, FF / 32, EE);
        transpose_fp16<<<g2, blk>>>(w2, (__half*)w2t, FF, DD);
    }

    // GEMM1: H = gelu(X @ W1 + b1): per group M=1024, K=512, N=2048
    {
        dim3 grid(FF / BN, CC / BM, BB * EE);
        moe_gemm<<<grid, 256, SMEM_TOTAL>>>(
            (const __half*)xh, (const __half*)w1t, b1,
            nullptr, (__half*)hh, DD, FF, 0);
    }
    // GEMM2: Y = H @ W2 + b2: per group M=1024, K=2048, N=512
    {
        dim3 grid(DD / BN, CC / BM, BB * EE);
        moe_gemm<<<grid, 256, SMEM_TOTAL>>>(
            (const __half*)hh, (const __half*)w2t, b2,
            out, nullptr, FF, DD, 1);
    }
}